// round 1
// baseline (speedup 1.0000x reference)
#include <cuda_runtime.h>
#include <cuda_bf16.h>
#include <cstdint>

// ---------------------------------------------------------------------------
// Problem constants (fixed shapes for GSLModel_LabelDistr)
// ---------------------------------------------------------------------------
#define NN    8192      // nodes
#define FEAT  512
#define CC    40        // classes
#define HID   1024
#define HOPS  4
#define K1P   2048      // padded split-K for GEMM1: 3*672=2016 -> 2048
#define K2P   3072      // split-K for GEMM2: 3*1024

// ---------------------------------------------------------------------------
// Scratch (static __device__ — no allocations allowed)
// ---------------------------------------------------------------------------
__device__ __nv_bfloat16 g_Abf[(size_t)NN * NN];          // sigmoid(adj) bf16, 128 MiB
__device__ float         g_dinv[NN];
__device__ __nv_bfloat16 g_curT[CC * NN];                 // B operand [n][k] for hop GEMM
__device__ __nv_bfloat16 g_A1[(size_t)NN * K1P];          // [X|dists] hi/lo/hi stacked
__device__ __nv_bfloat16 g_W1TS[(size_t)HID * K1P];       // W1^T hi/hi/lo stacked
__device__ __nv_bfloat16 g_A2[(size_t)NN * K2P];          // h hi/lo/hi stacked
__device__ __nv_bfloat16 g_W2TS[(size_t)CC * K2P];        // W2^T hi/hi/lo stacked
__device__ float         g_partial[(size_t)NN * HID];     // 32 MiB, reused

// ---------------------------------------------------------------------------
// Helpers
// ---------------------------------------------------------------------------
__device__ __forceinline__ uint32_t pack_bf2(float x, float y) {
    __nv_bfloat162 h = __floats2bfloat162_rn(x, y);   // .x = x (low half)
    return *reinterpret_cast<uint32_t*>(&h);
}
__device__ __forceinline__ void split_bf(float v, __nv_bfloat16& hi, __nv_bfloat16& lo) {
    hi = __float2bfloat16(v);
    lo = __float2bfloat16(v - __bfloat162float(hi));
}
__device__ __forceinline__ void mma_bf16(float c[4], uint32_t a0, uint32_t a1,
                                         uint32_t a2, uint32_t a3,
                                         uint32_t b0, uint32_t b1) {
    asm volatile(
        "mma.sync.aligned.m16n8k16.row.col.f32.bf16.bf16.f32 "
        "{%0,%1,%2,%3}, {%4,%5,%6,%7}, {%8,%9}, {%0,%1,%2,%3};\n"
        : "+f"(c[0]), "+f"(c[1]), "+f"(c[2]), "+f"(c[3])
        : "r"(a0), "r"(a1), "r"(a2), "r"(a3), "r"(b0), "r"(b1));
}

// ---------------------------------------------------------------------------
// K0: sigmoid(adj) -> bf16 cache + rowsum -> d_inv   (one block per row)
// ---------------------------------------------------------------------------
__global__ void k0_sigmoid_rowsum(const float* __restrict__ adj) {
    const int row = blockIdx.x;
    const int tid = threadIdx.x;
    const float4* src = reinterpret_cast<const float4*>(adj + (size_t)row * NN);
    uint2* dst = reinterpret_cast<uint2*>(g_Abf + (size_t)row * NN);
    float s = 0.f;
#pragma unroll
    for (int i = 0; i < 8; i++) {
        int idx = tid + i * 256;
        float4 v = src[idx];
        float s0 = 1.f / (1.f + __expf(-v.x));
        float s1 = 1.f / (1.f + __expf(-v.y));
        float s2 = 1.f / (1.f + __expf(-v.z));
        float s3 = 1.f / (1.f + __expf(-v.w));
        s += s0 + s1 + s2 + s3;
        dst[idx] = make_uint2(pack_bf2(s0, s1), pack_bf2(s2, s3));
    }
    // block reduce
    __shared__ float red[8];
    for (int o = 16; o; o >>= 1) s += __shfl_xor_sync(0xffffffffu, s, o);
    if ((tid & 31) == 0) red[tid >> 5] = s;
    __syncthreads();
    if (tid == 0) {
        float t = 0.f;
#pragma unroll
        for (int w = 0; w < 8; w++) t += red[w];
        g_dinv[row] = 1.f / (t + 1e-8f);
    }
}

// ---------------------------------------------------------------------------
// Prep kernels
// ---------------------------------------------------------------------------
__global__ void prep_curT0(const float* __restrict__ onehot) {
    int idx = blockIdx.x * 256 + threadIdx.x;          // over CC*NN
    if (idx >= CC * NN) return;
    int c = idx / NN, i = idx % NN;
    g_curT[idx] = __float2bfloat16(onehot[(size_t)i * CC + c]);
}

__global__ void prep_X(const float* __restrict__ X) {
    int idx = blockIdx.x * 256 + threadIdx.x;          // over NN*544 (512 X + 32 pad)
    if (idx >= NN * 544) return;
    int i = idx / 544, j = idx % 544;
    __nv_bfloat16* row = g_A1 + (size_t)i * K1P;
    if (j < FEAT) {
        __nv_bfloat16 hi, lo;
        split_bf(X[(size_t)i * FEAT + j], hi, lo);
        row[j] = hi; row[672 + j] = lo; row[1344 + j] = hi;
    } else {
        row[2016 + (j - FEAT)] = __float2bfloat16(0.f);
    }
}

__global__ void prep_W1TS(const float* __restrict__ W1) {   // W1 [672][1024]
    int idx = blockIdx.x * 256 + threadIdx.x;               // over HID*K1P
    if (idx >= HID * K1P) return;
    int n = idx / K1P, j = idx % K1P;
    __nv_bfloat16 o;
    if (j < 672) {
        o = __float2bfloat16(W1[(size_t)j * HID + n]);
    } else if (j < 1344) {
        o = __float2bfloat16(W1[(size_t)(j - 672) * HID + n]);
    } else if (j < 2016) {
        float v = W1[(size_t)(j - 1344) * HID + n];
        __nv_bfloat16 hi, lo; split_bf(v, hi, lo); o = lo;
    } else {
        o = __float2bfloat16(0.f);
    }
    g_W1TS[idx] = o;
}

__global__ void prep_W2TS(const float* __restrict__ W2) {   // W2 [1024][40]
    int idx = blockIdx.x * 256 + threadIdx.x;               // over CC*K2P
    if (idx >= CC * K2P) return;
    int n = idx / K2P, j = idx % K2P;
    __nv_bfloat16 o;
    if (j < 1024) {
        o = __float2bfloat16(W2[(size_t)j * CC + n]);
    } else if (j < 2048) {
        o = __float2bfloat16(W2[(size_t)(j - 1024) * CC + n]);
    } else {
        float v = W2[(size_t)(j - 2048) * CC + n];
        __nv_bfloat16 hi, lo; split_bf(v, hi, lo); o = lo;
    }
    g_W2TS[idx] = o;
}

// ---------------------------------------------------------------------------
// Generic bf16 GEMM:  D[M,N] += A[M,K] * BT[N,K]^T   (M=8192)
// Block: 128 rows x (N8*8) cols, 8 warps (warp = 16 rows x full N-tile range).
// gridDim = (M/128, N/(8*N8), ksplit);  writes fp32 partials per k-split.
// Register-staged single-buffer pipeline: issue next tile LDGs before MMAs.
// ---------------------------------------------------------------------------
template <int N8>
__global__ void gemm_bf16(const __nv_bfloat16* __restrict__ A, int lda,
                          const __nv_bfloat16* __restrict__ BT, int ldb,
                          float* __restrict__ partial, int Ntot, int Kper) {
    __shared__ __nv_bfloat16 As[128][72];
    __shared__ __nv_bfloat16 Bs[N8 * 8][72];

    const int tid  = threadIdx.x;
    const int warp = tid >> 5, lane = tid & 31;
    const int g = lane >> 2, t = lane & 3;
    const int mbase = blockIdx.x * 128;
    const int n0    = blockIdx.y * (N8 * 8);
    const int kbase = blockIdx.z * Kper;
    const int kend  = kbase + Kper;

    float acc[N8][4];
#pragma unroll
    for (int nt = 0; nt < N8; nt++)
#pragma unroll
        for (int q = 0; q < 4; q++) acc[nt][q] = 0.f;

    constexpr int BU = N8 * 8 * 16;              // uint2 count of B tile
    constexpr int BI = (BU + 255) / 256;
    constexpr bool BGUARD = (BU % 256) != 0;
    uint2 ra[8];
    uint2 rb[BI];

    auto loadregs = [&](int k0) {
#pragma unroll
        for (int i = 0; i < 8; i++) {
            int idx = tid + i * 256;
            ra[i] = *reinterpret_cast<const uint2*>(
                A + (size_t)(mbase + (idx >> 4)) * lda + k0 + (idx & 15) * 4);
        }
#pragma unroll
        for (int i = 0; i < BI; i++) {
            int idx = tid + i * 256;
            if (!BGUARD || idx < BU)
                rb[i] = *reinterpret_cast<const uint2*>(
                    BT + (size_t)(n0 + (idx >> 4)) * ldb + k0 + (idx & 15) * 4);
        }
    };

    loadregs(kbase);
    for (int k0 = kbase; k0 < kend; k0 += 64) {
        __syncthreads();
#pragma unroll
        for (int i = 0; i < 8; i++) {
            int idx = tid + i * 256;
            *reinterpret_cast<uint2*>(&As[idx >> 4][(idx & 15) * 4]) = ra[i];
        }
#pragma unroll
        for (int i = 0; i < BI; i++) {
            int idx = tid + i * 256;
            if (!BGUARD || idx < BU)
                *reinterpret_cast<uint2*>(&Bs[idx >> 4][(idx & 15) * 4]) = rb[i];
        }
        __syncthreads();
        if (k0 + 64 < kend) loadregs(k0 + 64);   // overlap latency with MMAs

#pragma unroll
        for (int kk = 0; kk < 4; kk++) {
            const int kc = kk * 16;
            uint32_t a0 = *reinterpret_cast<const uint32_t*>(&As[warp * 16 + g][kc + 2 * t]);
            uint32_t a1 = *reinterpret_cast<const uint32_t*>(&As[warp * 16 + g + 8][kc + 2 * t]);
            uint32_t a2 = *reinterpret_cast<const uint32_t*>(&As[warp * 16 + g][kc + 2 * t + 8]);
            uint32_t a3 = *reinterpret_cast<const uint32_t*>(&As[warp * 16 + g + 8][kc + 2 * t + 8]);
#pragma unroll
            for (int nt = 0; nt < N8; nt++) {
                uint32_t b0 = *reinterpret_cast<const uint32_t*>(&Bs[nt * 8 + g][kc + 2 * t]);
                uint32_t b1 = *reinterpret_cast<const uint32_t*>(&Bs[nt * 8 + g][kc + 2 * t + 8]);
                mma_bf16(acc[nt], a0, a1, a2, a3, b0, b1);
            }
        }
    }

    float* pbase = partial + (size_t)blockIdx.z * NN * Ntot;
#pragma unroll
    for (int nt = 0; nt < N8; nt++) {
        int row = mbase + warp * 16 + g;
        int col = n0 + nt * 8 + 2 * t;
        *reinterpret_cast<float2*>(pbase + (size_t)row * Ntot + col) =
            make_float2(acc[nt][0], acc[nt][1]);
        *reinterpret_cast<float2*>(pbase + (size_t)(row + 8) * Ntot + col) =
            make_float2(acc[nt][2], acc[nt][3]);
    }
}

// ---------------------------------------------------------------------------
// Hop epilogue: combine 4 k-split partials, scale by d_inv, softmax over 40,
// write dist (hi/lo/hi) into combined (g_A1) and bf16 curT for next hop.
// One warp per row.
// ---------------------------------------------------------------------------
__global__ void hop_epi(int h) {
    const int warp = threadIdx.x >> 5, lane = threadIdx.x & 31;
    const int i = blockIdx.x * 8 + warp;
    const int c0 = lane, c1 = lane + 32;
    const float di = g_dinv[i];

    float y0 = 0.f, y1 = 0.f;
#pragma unroll
    for (int p = 0; p < 4; p++) {
        y0 += g_partial[(size_t)p * NN * CC + (size_t)i * CC + c0];
        if (c1 < CC) y1 += g_partial[(size_t)p * NN * CC + (size_t)i * CC + c1];
    }
    y0 *= di; y1 *= di;

    float m = (c1 < CC) ? fmaxf(y0, y1) : y0;
    for (int o = 16; o; o >>= 1) m = fmaxf(m, __shfl_xor_sync(0xffffffffu, m, o));
    float e0 = __expf(y0 - m);
    float e1 = (c1 < CC) ? __expf(y1 - m) : 0.f;
    float s = e0 + e1;
    for (int o = 16; o; o >>= 1) s += __shfl_xor_sync(0xffffffffu, s, o);
    float inv = 1.f / s;

    __nv_bfloat16* row = g_A1 + (size_t)i * K1P;
    {
        float d = e0 * inv;
        __nv_bfloat16 hi, lo; split_bf(d, hi, lo);
        int j = FEAT + h * CC + c0;
        row[j] = hi; row[672 + j] = lo; row[1344 + j] = hi;
        if (h < HOPS - 1) g_curT[(size_t)c0 * NN + i] = __float2bfloat16(d);
    }
    if (c1 < CC) {
        float d = e1 * inv;
        __nv_bfloat16 hi, lo; split_bf(d, hi, lo);
        int j = FEAT + h * CC + c1;
        row[j] = hi; row[672 + j] = lo; row[1344 + j] = hi;
        if (h < HOPS - 1) g_curT[(size_t)c1 * NN + i] = __float2bfloat16(d);
    }
}

// ---------------------------------------------------------------------------
// MLP epilogue 1: relu(result + b1) -> split into A2 (hi | lo | hi)
// ---------------------------------------------------------------------------
__global__ void epi1(const float* __restrict__ b1) {
    int idx = blockIdx.x * 256 + threadIdx.x;           // over NN*HID
    int i = idx >> 10, n = idx & 1023;
    float v = g_partial[idx] + b1[n];
    v = fmaxf(v, 0.f);
    __nv_bfloat16 hi, lo; split_bf(v, hi, lo);
    __nv_bfloat16* row = g_A2 + (size_t)i * K2P;
    row[n] = hi; row[1024 + n] = lo; row[2048 + n] = hi;
}

// ---------------------------------------------------------------------------
// MLP epilogue 2: sum 4 k-split partials + b2 -> output fp32
// ---------------------------------------------------------------------------
__global__ void epi2(const float* __restrict__ b2, float* __restrict__ out) {
    int idx = blockIdx.x * 256 + threadIdx.x;           // over NN*CC
    if (idx >= NN * CC) return;
    float v = b2[idx % CC];
#pragma unroll
    for (int p = 0; p < 4; p++) v += g_partial[(size_t)p * NN * CC + idx];
    out[idx] = v;
}

// ---------------------------------------------------------------------------
// Launch
// ---------------------------------------------------------------------------
extern "C" void kernel_launch(void* const* d_in, const int* in_sizes, int n_in,
                              void* d_out, int out_size) {
    (void)in_sizes; (void)n_in; (void)out_size;
    const float* X      = (const float*)d_in[0];
    const float* onehot = (const float*)d_in[1];
    const float* adj    = (const float*)d_in[2];
    const float* W1     = (const float*)d_in[3];
    const float* b1     = (const float*)d_in[4];
    const float* W2     = (const float*)d_in[5];
    const float* b2     = (const float*)d_in[6];
    float* out = (float*)d_out;

    void *pAbf, *pCurT, *pA1, *pW1TS, *pA2, *pW2TS, *pPart;
    cudaGetSymbolAddress(&pAbf,  g_Abf);
    cudaGetSymbolAddress(&pCurT, g_curT);
    cudaGetSymbolAddress(&pA1,   g_A1);
    cudaGetSymbolAddress(&pW1TS, g_W1TS);
    cudaGetSymbolAddress(&pA2,   g_A2);
    cudaGetSymbolAddress(&pW2TS, g_W2TS);
    cudaGetSymbolAddress(&pPart, g_partial);

    // Phase 0: sigmoid + rowsum, B0 operand, MLP operand prep
    k0_sigmoid_rowsum<<<NN, 256>>>(adj);
    prep_curT0<<<(CC * NN + 255) / 256, 256>>>(onehot);
    prep_X<<<(NN * 544 + 255) / 256, 256>>>(X);
    prep_W1TS<<<(HID * K1P + 255) / 256, 256>>>(W1);
    prep_W2TS<<<(CC * K2P + 255) / 256, 256>>>(W2);

    // Phase 1: 4 label-propagation hops (split-K=4 GEMM + fused softmax epilogue)
    for (int h = 0; h < HOPS; h++) {
        gemm_bf16<5><<<dim3(64, 1, 4), 256>>>(
            (const __nv_bfloat16*)pAbf, NN,
            (const __nv_bfloat16*)pCurT, NN,
            (float*)pPart, CC, 2048);
        hop_epi<<<NN / 8, 256>>>(h);
    }

    // Phase 2: MLP layer 1 (split-bf16, K=2016 padded to 2048)
    gemm_bf16<8><<<dim3(64, 16, 1), 256>>>(
        (const __nv_bfloat16*)pA1, K1P,
        (const __nv_bfloat16*)pW1TS, K1P,
        (float*)pPart, HID, K1P);
    epi1<<<(NN * HID) / 256, 256>>>(b1);

    // Phase 3: MLP layer 2 (split-bf16, K=3072, split-K=4)
    gemm_bf16<5><<<dim3(64, 1, 4), 256>>>(
        (const __nv_bfloat16*)pA2, K2P,
        (const __nv_bfloat16*)pW2TS, K2P,
        (float*)pPart, CC, 768);
    epi2<<<(NN * CC + 255) / 256, 256>>>(b2, out);
}

// round 5
// speedup vs baseline: 1.3060x; 1.3060x over previous
#include <cuda_runtime.h>
#include <cuda_bf16.h>
#include <cstdint>

// ---------------------------------------------------------------------------
// Shapes (fixed)
// ---------------------------------------------------------------------------
#define NN    8192
#define FEAT  512
#define CC    40
#define HID   1024
#define HOPS  4
#define K1P   2048      // 3*672=2016 padded
#define K2P   3072      // 3*1024
#define ZSPLIT 4

// ---------------------------------------------------------------------------
// Static device scratch
// ---------------------------------------------------------------------------
__device__ __nv_bfloat16 g_Abf[(size_t)NN * NN];
__device__ float         g_dinv[NN];
__device__ __nv_bfloat16 g_curT[(size_t)64 * NN];          // padded to 64 rows
__device__ __nv_bfloat16 g_A1[(size_t)NN * K1P];           // [X|dists] hi/lo/hi
__device__ __nv_bfloat16 g_W1TS[(size_t)HID * K1P];        // W1^T hi/hi/lo
__device__ __nv_bfloat16 g_A2[(size_t)NN * K2P];           // relu(h) hi/lo/hi
__device__ __nv_bfloat16 g_W2TS[(size_t)64 * K2P];         // W2^T hi/hi/lo padded
__device__ float         g_partial[(size_t)ZSPLIT * NN * CC];

// ---------------------------------------------------------------------------
// Baseline-ISA helpers (sm_75/80 features only)
// ---------------------------------------------------------------------------
__device__ __forceinline__ uint32_t smem_u32(const void* p) {
    uint32_t a;
    asm("{ .reg .u64 t; cvta.to.shared.u64 t, %1; cvt.u32.u64 %0, t; }" : "=r"(a) : "l"(p));
    return a;
}
#define CP_ASYNC16(dst, src) \
    asm volatile("cp.async.cg.shared.global [%0], [%1], 16;" :: "r"(dst), "l"(src))
#define CP_COMMIT() asm volatile("cp.async.commit_group;" ::: "memory")
#define CP_WAIT(n)  asm volatile("cp.async.wait_group %0;" :: "n"(n) : "memory")

#define LDSM_X4(r0, r1, r2, r3, addr) \
    asm volatile("ldmatrix.sync.aligned.m8n8.x4.shared.b16 {%0,%1,%2,%3}, [%4];" \
                 : "=r"(r0), "=r"(r1), "=r"(r2), "=r"(r3) : "r"(addr))

__device__ __forceinline__ void mma16816(float c[4], uint32_t a0, uint32_t a1,
                                         uint32_t a2, uint32_t a3,
                                         uint32_t b0, uint32_t b1) {
    asm volatile(
        "mma.sync.aligned.m16n8k16.row.col.f32.bf16.bf16.f32 "
        "{%0,%1,%2,%3}, {%4,%5,%6,%7}, {%8,%9}, {%0,%1,%2,%3};\n"
        : "+f"(c[0]), "+f"(c[1]), "+f"(c[2]), "+f"(c[3])
        : "r"(a0), "r"(a1), "r"(a2), "r"(a3), "r"(b0), "r"(b1));
}

__device__ __forceinline__ uint32_t swz(uint32_t off) {
    return off ^ ((off >> 3) & 0x70);
}
__device__ __forceinline__ uint32_t pack_bf2(float x, float y) {
    __nv_bfloat162 h = __floats2bfloat162_rn(x, y);
    return *reinterpret_cast<uint32_t*>(&h);
}
__device__ __forceinline__ void split_bf(float v, __nv_bfloat16& hi, __nv_bfloat16& lo) {
    hi = __float2bfloat16(v);
    lo = __float2bfloat16(v - __bfloat162float(hi));
}
__device__ __forceinline__ float fast_sigmoid(float x) {
    float t;
    asm("tanh.approx.f32 %0, %1;" : "=f"(t) : "f"(0.5f * x));
    return fmaf(0.5f, t, 0.5f);
}

// ---------------------------------------------------------------------------
// K0: sigmoid(adj) -> bf16 + rowsum -> d_inv
// ---------------------------------------------------------------------------
__global__ void k0_sigmoid_rowsum(const float* __restrict__ adj) {
    const int row = blockIdx.x;
    const int tid = threadIdx.x;
    const float4* src = reinterpret_cast<const float4*>(adj + (size_t)row * NN);
    uint2* dst = reinterpret_cast<uint2*>(g_Abf + (size_t)row * NN);
    float s = 0.f;
#pragma unroll
    for (int i = 0; i < 8; i++) {
        int idx = tid + i * 256;
        float4 v = src[idx];
        float s0 = fast_sigmoid(v.x), s1 = fast_sigmoid(v.y);
        float s2 = fast_sigmoid(v.z), s3 = fast_sigmoid(v.w);
        s += s0 + s1 + s2 + s3;
        dst[idx] = make_uint2(pack_bf2(s0, s1), pack_bf2(s2, s3));
    }
    __shared__ float red[8];
    for (int o = 16; o; o >>= 1) s += __shfl_xor_sync(0xffffffffu, s, o);
    if ((tid & 31) == 0) red[tid >> 5] = s;
    __syncthreads();
    if (tid == 0) {
        float t = 0.f;
#pragma unroll
        for (int w = 0; w < 8; w++) t += red[w];
        g_dinv[row] = 1.f / (t + 1e-8f);
    }
}

// ---------------------------------------------------------------------------
// Prep kernels
// ---------------------------------------------------------------------------
__global__ void prep_curT0(const float* __restrict__ onehot) {
    int idx = blockIdx.x * 256 + threadIdx.x;      // over 64*NN
    int c = idx >> 13, i = idx & (NN - 1);
    float v = (c < CC) ? onehot[(size_t)i * CC + c] : 0.f;
    g_curT[idx] = __float2bfloat16(v);
}

__global__ void prep_X(const float* __restrict__ X) {
    int idx = blockIdx.x * 256 + threadIdx.x;      // over NN*544
    if (idx >= NN * 544) return;
    int i = idx / 544, j = idx % 544;
    __nv_bfloat16* row = g_A1 + (size_t)i * K1P;
    if (j < FEAT) {
        __nv_bfloat16 hi, lo;
        split_bf(X[(size_t)i * FEAT + j], hi, lo);
        row[j] = hi; row[672 + j] = lo; row[1344 + j] = hi;
    } else {
        row[2016 + (j - FEAT)] = __float2bfloat16(0.f);
    }
}

// W1 [672][1024] -> W1TS [1024][2048] (hi | hi | lo)
__global__ void prep_W1T(const float* __restrict__ W1) {
    __shared__ float t[32][33];
    int j0 = blockIdx.x * 32, n0 = blockIdx.y * 32;
#pragma unroll
    for (int r = threadIdx.y; r < 32; r += 8)
        t[r][threadIdx.x] = W1[(size_t)(j0 + r) * HID + n0 + threadIdx.x];
    __syncthreads();
#pragma unroll
    for (int r = threadIdx.y; r < 32; r += 8) {
        int n = n0 + r, j = j0 + threadIdx.x;
        float v = t[threadIdx.x][r];
        __nv_bfloat16 hi, lo; split_bf(v, hi, lo);
        __nv_bfloat16* rp = g_W1TS + (size_t)n * K1P;
        rp[j] = hi; rp[672 + j] = hi; rp[1344 + j] = lo;
    }
}
__global__ void pad_W1() {
    int idx = blockIdx.x * 256 + threadIdx.x;      // 1024*32
    int n = idx >> 5, j = 2016 + (idx & 31);
    g_W1TS[(size_t)n * K1P + j] = __float2bfloat16(0.f);
}

// W2 [1024][40] -> W2TS [64][3072] (hi | hi | lo), rows 40..63 zero
__global__ void prep_W2T(const float* __restrict__ W2) {
    __shared__ float t[64 * 40];
    int k0 = blockIdx.x * 64;
    for (int idx = threadIdx.x; idx < 64 * 40; idx += 256)
        t[idx] = W2[(size_t)k0 * CC + idx];
    __syncthreads();
    for (int idx = threadIdx.x; idx < 64 * 64; idx += 256) {
        int n = idx >> 6, j = idx & 63;
        float v = (n < CC) ? t[j * CC + n] : 0.f;
        __nv_bfloat16 hi, lo; split_bf(v, hi, lo);
        __nv_bfloat16* rp = g_W2TS + (size_t)n * K2P;
        rp[k0 + j] = hi; rp[1024 + k0 + j] = hi; rp[2048 + k0 + j] = lo;
    }
}

// ---------------------------------------------------------------------------
// HMMA GEMM: D[BM, BN] = A[BM, K] @ BT[BN, K]^T, both bf16 K-major.
// 256 threads, cp.async 3-stage pipeline, ldmatrix fragments, swizzled smem.
// Swizzle is applied to the FULL linear offset at every access (XOR does not
// commute with adding k-segment offsets).
// EPI=0: fp32 partial[z][row][0..CC)
// EPI=1: fused bias+relu+split -> g_A2
// ---------------------------------------------------------------------------
template <int BM, int BN, int WM, int WN, int EPI>
__global__ void __launch_bounds__(256, 2)
hgemm(const __nv_bfloat16* __restrict__ A, int lda,
      const __nv_bfloat16* __restrict__ BT, int ldb,
      float* __restrict__ outp, int Kper, const float* __restrict__ bias)
{
    constexpr int NST = 3;
    constexpr int ABYTES = BM * 128;           // per stage (64 k-elems = 128 B/row)
    constexpr int BBYTES = BN * 128;
    constexpr int SS = ABYTES + BBYTES;
    constexpr int WARPS_N = BN / WN;
    constexpr int MI = WM / 16;
    constexpr int NJ = WN / 8;
    constexpr int AP = (BM * 8) / 256;         // 16B segments: 8 per 128B row
    constexpr int BP = (BN * 8) / 256;

    extern __shared__ char dynsm[];
    const uint32_t sbase = (smem_u32(dynsm) + 1023u) & ~1023u;

    const int tid = threadIdx.x;
    const int w = tid >> 5, L = tid & 31;
    const int mbase = blockIdx.x * BM;
    const int n0 = blockIdx.y * BN;
    const int kbase = blockIdx.z * Kper;
    const int T = Kper >> 6;

    const int wm = (w / WARPS_N) * WM;
    const int wn = (w % WARPS_N) * WN;

    float acc[MI][NJ][4];
#pragma unroll
    for (int mi = 0; mi < MI; mi++)
#pragma unroll
        for (int nj = 0; nj < NJ; nj++)
#pragma unroll
            for (int q = 0; q < 4; q++) acc[mi][nj][q] = 0.f;

    // LINEAR (pre-swizzle) fragment offsets; swz applied at use.
    uint32_t alin[MI], blin[NJ / 2];
#pragma unroll
    for (int mi = 0; mi < MI; mi++)
        alin[mi] = (uint32_t)((wm + mi * 16 + (L & 15)) * 128 + ((L >> 4) * 16));
#pragma unroll
    for (int j = 0; j < NJ / 2; j++)
        blin[j] = (uint32_t)((wn + j * 16 + ((L >> 4) & 1) * 8 + (L & 7)) * 128
                             + (((L >> 3) & 1) * 16));

    auto load_tile = [&](int t, int s) {
        const int k0 = kbase + (t << 6);
        const uint32_t ab = sbase + s * SS;
        const char* ap = (const char*)A;
#pragma unroll
        for (int p = 0; p < AP; p++) {
            int idx = tid + p * 256;
            int row = idx >> 3, seg = idx & 7;
            CP_ASYNC16(ab + swz((uint32_t)(row * 128 + seg * 16)),
                       ap + ((size_t)(mbase + row) * lda + k0 + seg * 8) * 2);
        }
        const uint32_t bb = sbase + s * SS + ABYTES;
        const char* bp = (const char*)BT;
#pragma unroll
        for (int p = 0; p < BP; p++) {
            int idx = tid + p * 256;
            int row = idx >> 3, seg = idx & 7;
            CP_ASYNC16(bb + swz((uint32_t)(row * 128 + seg * 16)),
                       bp + ((size_t)(n0 + row) * ldb + k0 + seg * 8) * 2);
        }
    };

#pragma unroll
    for (int s = 0; s < NST - 1; s++) {
        if (s < T) load_tile(s, s);
        CP_COMMIT();
    }

    for (int k = 0; k < T; k++) {
        CP_WAIT(NST - 2);
        __syncthreads();
        if (k + NST - 1 < T) load_tile(k + NST - 1, (k + NST - 1) % NST);
        CP_COMMIT();

        const uint32_t ab = sbase + (k % NST) * SS;
        const uint32_t bb = ab + ABYTES;
#pragma unroll
        for (int s4 = 0; s4 < 4; s4++) {
            uint32_t a[MI][4];
#pragma unroll
            for (int mi = 0; mi < MI; mi++)
                LDSM_X4(a[mi][0], a[mi][1], a[mi][2], a[mi][3],
                        ab + swz(alin[mi] + s4 * 32));
            uint32_t b[NJ / 2][4];
#pragma unroll
            for (int j = 0; j < NJ / 2; j++)
                LDSM_X4(b[j][0], b[j][1], b[j][2], b[j][3],
                        bb + swz(blin[j] + s4 * 32));
#pragma unroll
            for (int mi = 0; mi < MI; mi++)
#pragma unroll
                for (int nj = 0; nj < NJ; nj++)
                    mma16816(acc[mi][nj], a[mi][0], a[mi][1], a[mi][2], a[mi][3],
                             b[nj >> 1][(nj & 1) * 2], b[nj >> 1][(nj & 1) * 2 + 1]);
        }
        __syncthreads();
    }

    // ---------------- epilogue ----------------
    const int g = L >> 2, t4 = L & 3;
    if (EPI == 0) {
        float* pbase = outp + (size_t)blockIdx.z * NN * CC;
#pragma unroll
        for (int mi = 0; mi < MI; mi++) {
            int r0 = mbase + wm + mi * 16 + g;
#pragma unroll
            for (int nj = 0; nj < NJ; nj++) {
                int col = wn + nj * 8 + 2 * t4;
                if (col < CC) {
                    *reinterpret_cast<float2*>(pbase + (size_t)r0 * CC + col) =
                        make_float2(acc[mi][nj][0], acc[mi][nj][1]);
                    *reinterpret_cast<float2*>(pbase + (size_t)(r0 + 8) * CC + col) =
                        make_float2(acc[mi][nj][2], acc[mi][nj][3]);
                }
            }
        }
    } else {
#pragma unroll
        for (int mi = 0; mi < MI; mi++) {
            int r0 = mbase + wm + mi * 16 + g;
#pragma unroll
            for (int nj = 0; nj < NJ; nj++) {
                int n = n0 + wn + nj * 8 + 2 * t4;
                float bx = bias[n], by = bias[n + 1];
#pragma unroll
                for (int half = 0; half < 2; half++) {
                    int row = r0 + half * 8;
                    float v0 = fmaxf(acc[mi][nj][half * 2] + bx, 0.f);
                    float v1 = fmaxf(acc[mi][nj][half * 2 + 1] + by, 0.f);
                    __nv_bfloat16 h0, l0, h1, l1;
                    split_bf(v0, h0, l0); split_bf(v1, h1, l1);
                    uint32_t hp = ((uint32_t)*(uint16_t*)&h1 << 16) | *(uint16_t*)&h0;
                    uint32_t lp = ((uint32_t)*(uint16_t*)&l1 << 16) | *(uint16_t*)&l0;
                    uint32_t* rp = (uint32_t*)(g_A2 + (size_t)row * K2P + n);
                    rp[0] = hp;
                    *(uint32_t*)((char*)rp + 1024 * 2) = lp;
                    *(uint32_t*)((char*)rp + 2048 * 2) = hp;
                }
            }
        }
    }
}

// ---------------------------------------------------------------------------
// Hop epilogue: sum ZSPLIT partials, d_inv scale, softmax(40), write A1 + curT
// ---------------------------------------------------------------------------
__global__ void hop_epi(int h) {
    const int warp = threadIdx.x >> 5, lane = threadIdx.x & 31;
    const int i = blockIdx.x * 8 + warp;
    const int c0 = lane, c1 = lane + 32;
    const float di = g_dinv[i];

    float y0 = 0.f, y1 = 0.f;
#pragma unroll
    for (int p = 0; p < ZSPLIT; p++) {
        y0 += g_partial[(size_t)p * NN * CC + (size_t)i * CC + c0];
        if (c1 < CC) y1 += g_partial[(size_t)p * NN * CC + (size_t)i * CC + c1];
    }
    y0 *= di; y1 *= di;

    float m = (c1 < CC) ? fmaxf(y0, y1) : y0;
    for (int o = 16; o; o >>= 1) m = fmaxf(m, __shfl_xor_sync(0xffffffffu, m, o));
    float e0 = __expf(y0 - m);
    float e1 = (c1 < CC) ? __expf(y1 - m) : 0.f;
    float s = e0 + e1;
    for (int o = 16; o; o >>= 1) s += __shfl_xor_sync(0xffffffffu, s, o);
    float inv = 1.f / s;

    __nv_bfloat16* row = g_A1 + (size_t)i * K1P;
    {
        float d = e0 * inv;
        __nv_bfloat16 hi, lo; split_bf(d, hi, lo);
        int j = FEAT + h * CC + c0;
        row[j] = hi; row[672 + j] = lo; row[1344 + j] = hi;
        if (h < HOPS - 1) g_curT[(size_t)c0 * NN + i] = __float2bfloat16(d);
    }
    if (c1 < CC) {
        float d = e1 * inv;
        __nv_bfloat16 hi, lo; split_bf(d, hi, lo);
        int j = FEAT + h * CC + c1;
        row[j] = hi; row[672 + j] = lo; row[1344 + j] = hi;
        if (h < HOPS - 1) g_curT[(size_t)c1 * NN + i] = __float2bfloat16(d);
    }
}

// ---------------------------------------------------------------------------
// Final epilogue: sum ZSPLIT partials + b2 -> out
// ---------------------------------------------------------------------------
__global__ void epi2(const float* __restrict__ b2, float* __restrict__ out) {
    int idx = blockIdx.x * 256 + threadIdx.x;
    if (idx >= NN * CC) return;
    float v = b2[idx % CC];
#pragma unroll
    for (int p = 0; p < ZSPLIT; p++) v += g_partial[(size_t)p * NN * CC + idx];
    out[idx] = v;
}

// ---------------------------------------------------------------------------
// Launch
// ---------------------------------------------------------------------------
extern "C" void kernel_launch(void* const* d_in, const int* in_sizes, int n_in,
                              void* d_out, int out_size) {
    (void)in_sizes; (void)n_in; (void)out_size;
    const float* X      = (const float*)d_in[0];
    const float* onehot = (const float*)d_in[1];
    const float* adj    = (const float*)d_in[2];
    const float* W1     = (const float*)d_in[3];
    const float* b1     = (const float*)d_in[4];
    const float* W2     = (const float*)d_in[5];
    const float* b2     = (const float*)d_in[6];
    float* out = (float*)d_out;

    void *pAbf, *pCurT, *pA1, *pW1TS, *pA2, *pW2TS, *pPart;
    cudaGetSymbolAddress(&pAbf,  g_Abf);
    cudaGetSymbolAddress(&pCurT, g_curT);
    cudaGetSymbolAddress(&pA1,   g_A1);
    cudaGetSymbolAddress(&pW1TS, g_W1TS);
    cudaGetSymbolAddress(&pA2,   g_A2);
    cudaGetSymbolAddress(&pW2TS, g_W2TS);
    cudaGetSymbolAddress(&pPart, g_partial);

    constexpr int SMEM_HOP = 1024 + 3 * (128 + 64) * 128;    // 74,752
    constexpr int SMEM_G1  = 1024 + 3 * (128 + 128) * 128;   // 99,328
    cudaFuncSetAttribute((const void*)hgemm<128, 64, 32, 32, 0>,
                         cudaFuncAttributeMaxDynamicSharedMemorySize, SMEM_HOP);
    cudaFuncSetAttribute((const void*)hgemm<128, 128, 64, 32, 1>,
                         cudaFuncAttributeMaxDynamicSharedMemorySize, SMEM_G1);

    // Phase 0
    k0_sigmoid_rowsum<<<NN, 256>>>(adj);
    prep_curT0<<<(64 * NN) / 256, 256>>>(onehot);
    prep_X<<<(NN * 544 + 255) / 256, 256>>>(X);
    prep_W1T<<<dim3(21, 32), dim3(32, 8)>>>(W1);
    pad_W1<<<(HID * 32) / 256, 256>>>();
    prep_W2T<<<16, 256>>>(W2);

    // Phase 1: 4 hops (split-K=4 HMMA GEMM + softmax epilogue)
    for (int h = 0; h < HOPS; h++) {
        hgemm<128, 64, 32, 32, 0><<<dim3(64, 1, ZSPLIT), 256, SMEM_HOP>>>(
            (const __nv_bfloat16*)pAbf, NN,
            (const __nv_bfloat16*)pCurT, NN,
            (float*)pPart, NN / ZSPLIT, nullptr);
        hop_epi<<<NN / 8, 256>>>(h);
    }

    // Phase 2: MLP layer 1, fused bias+relu+split epilogue
    hgemm<128, 128, 64, 32, 1><<<dim3(64, 8, 1), 256, SMEM_G1>>>(
        (const __nv_bfloat16*)pA1, K1P,
        (const __nv_bfloat16*)pW1TS, K1P,
        nullptr, K1P, b1);

    // Phase 3: MLP layer 2 (split-K=4)
    hgemm<128, 64, 32, 32, 0><<<dim3(64, 1, ZSPLIT), 256, SMEM_HOP>>>(
        (const __nv_bfloat16*)pA2, K2P,
        (const __nv_bfloat16*)pW2TS, K2P,
        (float*)pPart, K2P / ZSPLIT, nullptr);
    epi2<<<(NN * CC + 255) / 256, 256>>>(b2, out);
}

// round 6
// speedup vs baseline: 1.9714x; 1.5096x over previous
#include <cuda_runtime.h>
#include <cuda_bf16.h>
#include <cuda_fp8.h>
#include <cstdint>

// ---------------------------------------------------------------------------
// Shapes (fixed)
// ---------------------------------------------------------------------------
#define NN    8192
#define FEAT  512
#define CC    40
#define HID   1024
#define HOPS  4
#define K1P   1728      // 3*512 (X split) + 160 (dists raw) + 32 pad
#define K2P   3072      // 3*1024
#define ZSPLIT 4

// ---------------------------------------------------------------------------
// Static device scratch
// ---------------------------------------------------------------------------
// Adjacency, e4m3, fragment-permuted: [rt 0..512)[ct 0..256)[512B tile]
// tile byte (g*4+t)*16 + (kh*2+rh)*4 + b  for element (r = rt*16+rh*8+g,
// k = ct*32 + kh*16 + t*4 + b)
__device__ uint8_t       g_Afp8[(size_t)NN * NN];
// cur distribution, e4m3, permuted: [ct 0..256)[nt 0..4)[512B tile]
// tile byte (g*4+t)*16 + (nh*2+kh)*4 + b for (n = nt*16+nh*8+g, k-in-tile)
__device__ uint8_t       g_Bp[(size_t)256 * 4 * 512];
__device__ float         g_dinv[NN];
__device__ __nv_bfloat16 g_A1[(size_t)NN * K1P];       // [Xhi|Xlo|Xhi|dists|pad]
__device__ __nv_bfloat16 g_W1TS[(size_t)HID * K1P];    // [Whi|Whi|Wlo|Wd|0]
__device__ __nv_bfloat16 g_A2[(size_t)NN * K2P];       // relu(h) hi/lo/hi
__device__ __nv_bfloat16 g_W2TS[(size_t)64 * K2P];     // W2^T hi/hi/lo padded
__device__ float         g_partial[(size_t)ZSPLIT * NN * CC];

// ---------------------------------------------------------------------------
// Helpers
// ---------------------------------------------------------------------------
__device__ __forceinline__ uint32_t smem_u32(const void* p) {
    uint32_t a;
    asm("{ .reg .u64 t; cvta.to.shared.u64 t, %1; cvt.u32.u64 %0, t; }" : "=r"(a) : "l"(p));
    return a;
}
#define CP_ASYNC16(dst, src) \
    asm volatile("cp.async.cg.shared.global [%0], [%1], 16;" :: "r"(dst), "l"(src))
#define CP_COMMIT() asm volatile("cp.async.commit_group;" ::: "memory")
#define CP_WAIT(n)  asm volatile("cp.async.wait_group %0;" :: "n"(n) : "memory")

#define LDSM_X4(r0, r1, r2, r3, addr) \
    asm volatile("ldmatrix.sync.aligned.m8n8.x4.shared.b16 {%0,%1,%2,%3}, [%4];" \
                 : "=r"(r0), "=r"(r1), "=r"(r2), "=r"(r3) : "r"(addr))

__device__ __forceinline__ void mma16816(float c[4], uint32_t a0, uint32_t a1,
                                         uint32_t a2, uint32_t a3,
                                         uint32_t b0, uint32_t b1) {
    asm volatile(
        "mma.sync.aligned.m16n8k16.row.col.f32.bf16.bf16.f32 "
        "{%0,%1,%2,%3}, {%4,%5,%6,%7}, {%8,%9}, {%0,%1,%2,%3};\n"
        : "+f"(c[0]), "+f"(c[1]), "+f"(c[2]), "+f"(c[3])
        : "r"(a0), "r"(a1), "r"(a2), "r"(a3), "r"(b0), "r"(b1));
}
__device__ __forceinline__ void mma_fp8(float c[4], uint32_t a0, uint32_t a1,
                                        uint32_t a2, uint32_t a3,
                                        uint32_t b0, uint32_t b1) {
    asm volatile(
        "mma.sync.aligned.m16n8k32.row.col.f32.e4m3.e4m3.f32 "
        "{%0,%1,%2,%3}, {%4,%5,%6,%7}, {%8,%9}, {%0,%1,%2,%3};\n"
        : "+f"(c[0]), "+f"(c[1]), "+f"(c[2]), "+f"(c[3])
        : "r"(a0), "r"(a1), "r"(a2), "r"(a3), "r"(b0), "r"(b1));
}

__device__ __forceinline__ uint32_t swz(uint32_t off) {
    return off ^ ((off >> 3) & 0x70);
}
__device__ __forceinline__ void split_bf(float v, __nv_bfloat16& hi, __nv_bfloat16& lo) {
    hi = __float2bfloat16(v);
    lo = __float2bfloat16(v - __bfloat162float(hi));
}
__device__ __forceinline__ float fast_sigmoid(float x) {
    float t;
    asm("tanh.approx.f32 %0, %1;" : "=f"(t) : "f"(0.5f * x));
    return fmaf(0.5f, t, 0.5f);
}
__device__ __forceinline__ uint8_t to_fp8(float v) {
    return (uint8_t)__nv_cvt_float_to_fp8(v, __NV_SATFINITE, __NV_E4M3);
}

// ---------------------------------------------------------------------------
// K0: sigmoid(adj) -> fp8 fragment-permuted + rowsum -> d_inv
// One block per 16-row group; stages permuted tiles in smem, streams linearly.
// ---------------------------------------------------------------------------
__global__ __launch_bounds__(256) void k0_fp8(const float* __restrict__ adj) {
    __shared__ uint32_t stage[2048];          // 8 KB = 16 tiles
    __shared__ float red[16];
    const int rt = blockIdx.x;                // 0..511
    const int tid = threadIdx.x;
    const int row = tid >> 4;                 // 0..15
    const int cg = tid & 15;
    const int g = row & 7, rh = row >> 3;
    const float* src = adj + (size_t)(rt * 16 + row) * NN;
    uint8_t* dstbase = g_Afp8 + (size_t)rt * 256 * 512;
    float s = 0.f;

    for (int cit = 0; cit < 16; cit++) {
#pragma unroll
        for (int it = 0; it < 8; it++) {
            int col4 = cg + it * 16;          // 0..127 (float4 index in 512-col chunk)
            float4 v = *reinterpret_cast<const float4*>(src + cit * 512 + col4 * 4);
            float s0 = fast_sigmoid(v.x), s1 = fast_sigmoid(v.y);
            float s2 = fast_sigmoid(v.z), s3 = fast_sigmoid(v.w);
            s += s0 + s1 + s2 + s3;
            uint32_t wv = (uint32_t)to_fp8(s0) | ((uint32_t)to_fp8(s1) << 8)
                        | ((uint32_t)to_fp8(s2) << 16) | ((uint32_t)to_fp8(s3) << 24);
            int ctl = col4 >> 3, t = col4 & 3, kh = (col4 >> 2) & 1;
            stage[ctl * 128 + (g * 4 + t) * 4 + (kh * 2 + rh)] = wv;
        }
        __syncthreads();
        uint4* dst = reinterpret_cast<uint4*>(dstbase + (size_t)cit * 8192);
        const uint4* sp = reinterpret_cast<const uint4*>(stage);
        dst[tid] = sp[tid];
        dst[tid + 256] = sp[tid + 256];
        __syncthreads();
    }
    for (int o = 8; o; o >>= 1) s += __shfl_xor_sync(0xffffffffu, s, o);
    if (cg == 0) red[row] = s;
    __syncthreads();
    if (tid < 16) g_dinv[rt * 16 + tid] = 1.f / (red[tid] + 1e-8f);
}

// ---------------------------------------------------------------------------
// Prep: initial cur distribution (onehot) -> g_Bp, rows >= CC zero
// ---------------------------------------------------------------------------
__global__ void prep_B0(const float* __restrict__ onehot) {
    int idx = blockIdx.x * 256 + threadIdx.x;     // 64 * 2048
    int c = idx >> 11, i4 = idx & 2047;           // i4: word (4 nodes)
    int ct = i4 >> 3, t = i4 & 3, kh = (i4 >> 2) & 1;
    uint32_t addr = (uint32_t)((ct * 4 + (c >> 4)) * 512
                  + ((c & 7) * 4 + t) * 16 + (((c >> 3) & 1) * 2 + kh) * 4);
    uint32_t v = 0;
    if (c < CC) {
#pragma unroll
        for (int b = 0; b < 4; b++)
            if (onehot[(size_t)(i4 * 4 + b) * CC + c] != 0.f) v |= 0x38u << (8 * b);
    }
    *reinterpret_cast<uint32_t*>(g_Bp + addr) = v;
}

__global__ void prep_X(const float* __restrict__ X) {
    int idx = blockIdx.x * 256 + threadIdx.x;      // over NN*544
    if (idx >= NN * 544) return;
    int i = idx / 544, j = idx % 544;
    __nv_bfloat16* row = g_A1 + (size_t)i * K1P;
    if (j < FEAT) {
        __nv_bfloat16 hi, lo;
        split_bf(X[(size_t)i * FEAT + j], hi, lo);
        row[j] = hi; row[512 + j] = lo; row[1024 + j] = hi;
    } else {
        row[1696 + (j - FEAT)] = __float2bfloat16(0.f);   // pad cols 1696..1727
    }
}

// W1 [672][1024] -> W1TS [1024][1728]
__global__ void prep_W1T(const float* __restrict__ W1) {
    __shared__ float t[32][33];
    int j0 = blockIdx.x * 32, n0 = blockIdx.y * 32;
#pragma unroll
    for (int r = threadIdx.y; r < 32; r += 8)
        t[r][threadIdx.x] = W1[(size_t)(j0 + r) * HID + n0 + threadIdx.x];
    __syncthreads();
#pragma unroll
    for (int r = threadIdx.y; r < 32; r += 8) {
        int n = n0 + r, j = j0 + threadIdx.x;
        float v = t[threadIdx.x][r];
        __nv_bfloat16* rp = g_W1TS + (size_t)n * K1P;
        if (j < 512) {
            __nv_bfloat16 hi, lo; split_bf(v, hi, lo);
            rp[j] = hi; rp[512 + j] = hi; rp[1024 + j] = lo;
        } else {
            rp[1536 + (j - 512)] = __float2bfloat16(v);
        }
    }
}
__global__ void pad_W1() {
    int idx = blockIdx.x * 256 + threadIdx.x;      // 1024*32
    int n = idx >> 5, j = 1696 + (idx & 31);
    g_W1TS[(size_t)n * K1P + j] = __float2bfloat16(0.f);
}

// W2 [1024][40] -> W2TS [64][3072] (hi | hi | lo), rows 40..63 zero
__global__ void prep_W2T(const float* __restrict__ W2) {
    __shared__ float t[64 * 40];
    int k0 = blockIdx.x * 64;
    for (int idx = threadIdx.x; idx < 64 * 40; idx += 256)
        t[idx] = W2[(size_t)k0 * CC + idx];
    __syncthreads();
    for (int idx = threadIdx.x; idx < 64 * 64; idx += 256) {
        int n = idx >> 6, j = idx & 63;
        float v = (n < CC) ? t[j * CC + n] : 0.f;
        __nv_bfloat16 hi, lo; split_bf(v, hi, lo);
        __nv_bfloat16* rp = g_W2TS + (size_t)n * K2P;
        rp[k0 + j] = hi; rp[1024 + k0 + j] = hi; rp[2048 + k0 + j] = lo;
    }
}

// ---------------------------------------------------------------------------
// fp8 hop GEMM: partial[z] = Afp8[128 rows, Kper] @ Bp[64, Kper]^T
// Pre-permuted operands: fragment load = 1x LDS.128. 256 thr, 8 warps (4x2),
// 3-stage cp.async, stage = 128 k (4 tiles).
// ---------------------------------------------------------------------------
__global__ void __launch_bounds__(256, 3)
fp8gemm(const uint8_t* __restrict__ Ap, const uint8_t* __restrict__ Bp,
        float* __restrict__ outp, int Kper)
{
    constexpr int NST = 3;
    constexpr int ASTG = 16384, BSTG = 8192, SS = ASTG + BSTG;
    extern __shared__ char dynsm[];
    const uint32_t sbase = (smem_u32(dynsm) + 1023u) & ~1023u;

    const int tid = threadIdx.x;
    const int w = tid >> 5, L = tid & 31;
    const int wrow = w >> 1, wcol = w & 1;
    const int rt0 = blockIdx.x * 8;
    const int mbase = blockIdx.x * 128;
    const int ct0 = blockIdx.z * (Kper >> 5);
    const int T = Kper >> 7;                       // stages of 128 k

    float acc[2][4][4];
#pragma unroll
    for (int mi = 0; mi < 2; mi++)
#pragma unroll
        for (int nj = 0; nj < 4; nj++)
#pragma unroll
            for (int q = 0; q < 4; q++) acc[mi][nj][q] = 0.f;

    auto load_tile = [&](int t, int s) {
        const int cts = ct0 + t * 4;
        const uint32_t as = sbase + s * SS;
        const int rt_l = tid >> 5;
        const int off = (tid & 31) * 16;
        const uint8_t* ag = Ap + ((size_t)(rt0 + rt_l) * 256 + cts) * 512;
#pragma unroll
        for (int i = 0; i < 4; i++)
            CP_ASYNC16(as + rt_l * 2048 + off + i * 512, ag + off + i * 512);
        const uint32_t bs = sbase + s * SS + ASTG;
        const uint8_t* bg = Bp + (size_t)cts * 4 * 512;
        CP_ASYNC16(bs + tid * 32,      bg + tid * 32);
        CP_ASYNC16(bs + tid * 32 + 16, bg + tid * 32 + 16);
    };

#pragma unroll
    for (int s = 0; s < NST - 1; s++) {
        if (s < T) load_tile(s, s);
        CP_COMMIT();
    }

    for (int k = 0; k < T; k++) {
        CP_WAIT(NST - 2);
        __syncthreads();
        if (k + NST - 1 < T) load_tile(k + NST - 1, (k + NST - 1) % NST);
        CP_COMMIT();

        const uint32_t as = sbase + (k % NST) * SS;
        const uint32_t bs = as + ASTG;
#pragma unroll
        for (int ctl = 0; ctl < 4; ctl++) {
            uint4 av[2];
#pragma unroll
            for (int mi = 0; mi < 2; mi++)
                av[mi] = *reinterpret_cast<const uint4*>(
                    (const char*)nullptr +
                    0) , av[mi] = *(const uint4*)__cvta_shared_to_generic(
                        (size_t)(as + ((wrow * 2 + mi) * 4 + ctl) * 512 + L * 16));
            uint4 bv[2];
#pragma unroll
            for (int j = 0; j < 2; j++)
                bv[j] = *(const uint4*)__cvta_shared_to_generic(
                    (size_t)(bs + (ctl * 4 + wcol * 2 + j) * 512 + L * 16));
#pragma unroll
            for (int mi = 0; mi < 2; mi++)
#pragma unroll
                for (int j = 0; j < 2; j++) {
                    mma_fp8(acc[mi][j * 2 + 0], av[mi].x, av[mi].y, av[mi].z, av[mi].w,
                            bv[j].x, bv[j].y);
                    mma_fp8(acc[mi][j * 2 + 1], av[mi].x, av[mi].y, av[mi].z, av[mi].w,
                            bv[j].z, bv[j].w);
                }
        }
        __syncthreads();
    }

    const int g = L >> 2, t4 = L & 3;
    float* pbase = outp + (size_t)blockIdx.z * NN * CC;
#pragma unroll
    for (int mi = 0; mi < 2; mi++) {
        int r0 = mbase + wrow * 32 + mi * 16 + g;
#pragma unroll
        for (int nj = 0; nj < 4; nj++) {
            int col = wcol * 32 + (nj >> 1) * 16 + (nj & 1) * 8 + 2 * t4;
            if (col < CC) {
                *reinterpret_cast<float2*>(pbase + (size_t)r0 * CC + col) =
                    make_float2(acc[mi][nj][0], acc[mi][nj][1]);
                *reinterpret_cast<float2*>(pbase + (size_t)(r0 + 8) * CC + col) =
                    make_float2(acc[mi][nj][2], acc[mi][nj][3]);
            }
        }
    }
}

// ---------------------------------------------------------------------------
// bf16 HMMA GEMM (MLP): D[BM,BN] = A[BM,K] @ BT[BN,K]^T  (round-5 proven)
// EPI=0: fp32 partial[z][row][0..CC);  EPI=1: bias+relu+split -> g_A2
// ---------------------------------------------------------------------------
template <int BM, int BN, int WM, int WN, int EPI>
__global__ void __launch_bounds__(256, 2)
hgemm(const __nv_bfloat16* __restrict__ A, int lda,
      const __nv_bfloat16* __restrict__ BT, int ldb,
      float* __restrict__ outp, int Kper, const float* __restrict__ bias)
{
    constexpr int NST = 3;
    constexpr int ABYTES = BM * 128;
    constexpr int BBYTES = BN * 128;
    constexpr int SS = ABYTES + BBYTES;
    constexpr int WARPS_N = BN / WN;
    constexpr int MI = WM / 16;
    constexpr int NJ = WN / 8;
    constexpr int AP = (BM * 8) / 256;
    constexpr int BP = (BN * 8) / 256;

    extern __shared__ char dynsm[];
    const uint32_t sbase = (smem_u32(dynsm) + 1023u) & ~1023u;

    const int tid = threadIdx.x;
    const int w = tid >> 5, L = tid & 31;
    const int mbase = blockIdx.x * BM;
    const int n0 = blockIdx.y * BN;
    const int kbase = blockIdx.z * Kper;
    const int T = Kper >> 6;

    const int wm = (w / WARPS_N) * WM;
    const int wn = (w % WARPS_N) * WN;

    float acc[MI][NJ][4];
#pragma unroll
    for (int mi = 0; mi < MI; mi++)
#pragma unroll
        for (int nj = 0; nj < NJ; nj++)
#pragma unroll
            for (int q = 0; q < 4; q++) acc[mi][nj][q] = 0.f;

    uint32_t alin[MI], blin[NJ / 2];
#pragma unroll
    for (int mi = 0; mi < MI; mi++)
        alin[mi] = (uint32_t)((wm + mi * 16 + (L & 15)) * 128 + ((L >> 4) * 16));
#pragma unroll
    for (int j = 0; j < NJ / 2; j++)
        blin[j] = (uint32_t)((wn + j * 16 + ((L >> 4) & 1) * 8 + (L & 7)) * 128
                             + (((L >> 3) & 1) * 16));

    auto load_tile = [&](int t, int s) {
        const int k0 = kbase + (t << 6);
        const uint32_t ab = sbase + s * SS;
        const char* ap = (const char*)A;
#pragma unroll
        for (int p = 0; p < AP; p++) {
            int idx = tid + p * 256;
            int row = idx >> 3, seg = idx & 7;
            CP_ASYNC16(ab + swz((uint32_t)(row * 128 + seg * 16)),
                       ap + ((size_t)(mbase + row) * lda + k0 + seg * 8) * 2);
        }
        const uint32_t bb = sbase + s * SS + ABYTES;
        const char* bp = (const char*)BT;
#pragma unroll
        for (int p = 0; p < BP; p++) {
            int idx = tid + p * 256;
            int row = idx >> 3, seg = idx & 7;
            CP_ASYNC16(bb + swz((uint32_t)(row * 128 + seg * 16)),
                       bp + ((size_t)(n0 + row) * ldb + k0 + seg * 8) * 2);
        }
    };

#pragma unroll
    for (int s = 0; s < NST - 1; s++) {
        if (s < T) load_tile(s, s);
        CP_COMMIT();
    }

    for (int k = 0; k < T; k++) {
        CP_WAIT(NST - 2);
        __syncthreads();
        if (k + NST - 1 < T) load_tile(k + NST - 1, (k + NST - 1) % NST);
        CP_COMMIT();

        const uint32_t ab = sbase + (k % NST) * SS;
        const uint32_t bb = ab + ABYTES;
#pragma unroll
        for (int s4 = 0; s4 < 4; s4++) {
            uint32_t a[MI][4];
#pragma unroll
            for (int mi = 0; mi < MI; mi++)
                LDSM_X4(a[mi][0], a[mi][1], a[mi][2], a[mi][3],
                        ab + swz(alin[mi] + s4 * 32));
            uint32_t b[NJ / 2][4];
#pragma unroll
            for (int j = 0; j < NJ / 2; j++)
                LDSM_X4(b[j][0], b[j][1], b[j][2], b[j][3],
                        bb + swz(blin[j] + s4 * 32));
#pragma unroll
            for (int mi = 0; mi < MI; mi++)
#pragma unroll
                for (int nj = 0; nj < NJ; nj++)
                    mma16816(acc[mi][nj], a[mi][0], a[mi][1], a[mi][2], a[mi][3],
                             b[nj >> 1][(nj & 1) * 2], b[nj >> 1][(nj & 1) * 2 + 1]);
        }
        __syncthreads();
    }

    const int g = L >> 2, t4 = L & 3;
    if (EPI == 0) {
        float* pbase = outp + (size_t)blockIdx.z * NN * CC;
#pragma unroll
        for (int mi = 0; mi < MI; mi++) {
            int r0 = mbase + wm + mi * 16 + g;
#pragma unroll
            for (int nj = 0; nj < NJ; nj++) {
                int col = wn + nj * 8 + 2 * t4;
                if (col < CC) {
                    *reinterpret_cast<float2*>(pbase + (size_t)r0 * CC + col) =
                        make_float2(acc[mi][nj][0], acc[mi][nj][1]);
                    *reinterpret_cast<float2*>(pbase + (size_t)(r0 + 8) * CC + col) =
                        make_float2(acc[mi][nj][2], acc[mi][nj][3]);
                }
            }
        }
    } else {
#pragma unroll
        for (int mi = 0; mi < MI; mi++) {
            int r0 = mbase + wm + mi * 16 + g;
#pragma unroll
            for (int nj = 0; nj < NJ; nj++) {
                int n = n0 + wn + nj * 8 + 2 * t4;
                float bx = bias[n], by = bias[n + 1];
#pragma unroll
                for (int half = 0; half < 2; half++) {
                    int row = r0 + half * 8;
                    float v0 = fmaxf(acc[mi][nj][half * 2] + bx, 0.f);
                    float v1 = fmaxf(acc[mi][nj][half * 2 + 1] + by, 0.f);
                    __nv_bfloat16 h0, l0, h1, l1;
                    split_bf(v0, h0, l0); split_bf(v1, h1, l1);
                    uint32_t hp = ((uint32_t)*(uint16_t*)&h1 << 16) | *(uint16_t*)&h0;
                    uint32_t lp = ((uint32_t)*(uint16_t*)&l1 << 16) | *(uint16_t*)&l0;
                    uint32_t* rp = (uint32_t*)(g_A2 + (size_t)row * K2P + n);
                    rp[0] = hp;
                    *(uint32_t*)((char*)rp + 1024 * 2) = lp;
                    *(uint32_t*)((char*)rp + 2048 * 2) = hp;
                }
            }
        }
    }
}

// ---------------------------------------------------------------------------
// Hop epilogue: sum partials, d_inv, softmax(40) -> A1 dists + fp8 g_Bp
// ---------------------------------------------------------------------------
__global__ void hop_epi(int h) {
    const int warp = threadIdx.x >> 5, lane = threadIdx.x & 31;
    const int i = blockIdx.x * 8 + warp;
    const int c0 = lane, c1 = lane + 32;
    const float di = g_dinv[i];

    float y0 = 0.f, y1 = 0.f;
#pragma unroll
    for (int p = 0; p < ZSPLIT; p++) {
        y0 += g_partial[(size_t)p * NN * CC + (size_t)i * CC + c0];
        if (c1 < CC) y1 += g_partial[(size_t)p * NN * CC + (size_t)i * CC + c1];
    }
    y0 *= di; y1 *= di;

    float m = (c1 < CC) ? fmaxf(y0, y1) : y0;
    for (int o = 16; o; o >>= 1) m = fmaxf(m, __shfl_xor_sync(0xffffffffu, m, o));
    float e0 = __expf(y0 - m);
    float e1 = (c1 < CC) ? __expf(y1 - m) : 0.f;
    float s = e0 + e1;
    for (int o = 16; o; o >>= 1) s += __shfl_xor_sync(0xffffffffu, s, o);
    float inv = 1.f / s;

    const int ct = i >> 5, t = (i >> 2) & 3, kh = (i >> 4) & 1, b = i & 3;
    __nv_bfloat16* row = g_A1 + (size_t)i * K1P;
    {
        float d = e0 * inv;
        row[1536 + h * CC + c0] = __float2bfloat16(d);
        if (h < HOPS - 1) {
            uint32_t addr = (uint32_t)((ct * 4 + (c0 >> 4)) * 512
                          + ((c0 & 7) * 4 + t) * 16 + (((c0 >> 3) & 1) * 2 + kh) * 4 + b);
            g_Bp[addr] = to_fp8(d);
        }
    }
    if (c1 < CC) {
        float d = e1 * inv;
        row[1536 + h * CC + c1] = __float2bfloat16(d);
        if (h < HOPS - 1) {
            uint32_t addr = (uint32_t)((ct * 4 + (c1 >> 4)) * 512
                          + ((c1 & 7) * 4 + t) * 16 + (((c1 >> 3) & 1) * 2 + kh) * 4 + b);
            g_Bp[addr] = to_fp8(d);
        }
    }
}

// ---------------------------------------------------------------------------
// Final epilogue: sum partials + b2 -> out
// ---------------------------------------------------------------------------
__global__ void epi2(const float* __restrict__ b2, float* __restrict__ out) {
    int idx = blockIdx.x * 256 + threadIdx.x;
    if (idx >= NN * CC) return;
    float v = b2[idx % CC];
#pragma unroll
    for (int p = 0; p < ZSPLIT; p++) v += g_partial[(size_t)p * NN * CC + idx];
    out[idx] = v;
}

// ---------------------------------------------------------------------------
// Launch
// ---------------------------------------------------------------------------
extern "C" void kernel_launch(void* const* d_in, const int* in_sizes, int n_in,
                              void* d_out, int out_size) {
    (void)in_sizes; (void)n_in; (void)out_size;
    const float* X      = (const float*)d_in[0];
    const float* onehot = (const float*)d_in[1];
    const float* adj    = (const float*)d_in[2];
    const float* W1     = (const float*)d_in[3];
    const float* b1     = (const float*)d_in[4];
    const float* W2     = (const float*)d_in[5];
    const float* b2     = (const float*)d_in[6];
    float* out = (float*)d_out;

    void *pAfp8, *pBp, *pA1, *pW1TS, *pA2, *pW2TS, *pPart;
    cudaGetSymbolAddress(&pAfp8, g_Afp8);
    cudaGetSymbolAddress(&pBp,   g_Bp);
    cudaGetSymbolAddress(&pA1,   g_A1);
    cudaGetSymbolAddress(&pW1TS, g_W1TS);
    cudaGetSymbolAddress(&pA2,   g_A2);
    cudaGetSymbolAddress(&pW2TS, g_W2TS);
    cudaGetSymbolAddress(&pPart, g_partial);

    constexpr int SMEM_FP8 = 1024 + 3 * (16384 + 8192);      // 74,752
    constexpr int SMEM_G1  = 1024 + 3 * (128 + 128) * 128;   // 99,328
    constexpr int SMEM_G2  = 1024 + 3 * (128 + 64) * 128;    // 74,752
    cudaFuncSetAttribute((const void*)fp8gemm,
                         cudaFuncAttributeMaxDynamicSharedMemorySize, SMEM_FP8);
    cudaFuncSetAttribute((const void*)hgemm<128, 128, 64, 32, 1>,
                         cudaFuncAttributeMaxDynamicSharedMemorySize, SMEM_G1);
    cudaFuncSetAttribute((const void*)hgemm<128, 64, 32, 32, 0>,
                         cudaFuncAttributeMaxDynamicSharedMemorySize, SMEM_G2);

    // Phase 0
    k0_fp8<<<NN / 16, 256>>>(adj);
    prep_B0<<<(64 * 2048) / 256, 256>>>(onehot);
    prep_X<<<(NN * 544 + 255) / 256, 256>>>(X);
    prep_W1T<<<dim3(21, 32), dim3(32, 8)>>>(W1);
    pad_W1<<<(HID * 32) / 256, 256>>>();
    prep_W2T<<<16, 256>>>(W2);

    // Phase 1: 4 hops (fp8 split-K=4 GEMM + softmax epilogue)
    for (int h = 0; h < HOPS; h++) {
        fp8gemm<<<dim3(64, 1, ZSPLIT), 256, SMEM_FP8>>>(
            (const uint8_t*)pAfp8, (const uint8_t*)pBp,
            (float*)pPart, NN / ZSPLIT);
        hop_epi<<<NN / 8, 256>>>(h);
    }

    // Phase 2: MLP layer 1 (K=1728), fused bias+relu+split epilogue
    hgemm<128, 128, 64, 32, 1><<<dim3(64, 8, 1), 256, SMEM_G1>>>(
        (const __nv_bfloat16*)pA1, K1P,
        (const __nv_bfloat16*)pW1TS, K1P,
        nullptr, K1P, b1);

    // Phase 3: MLP layer 2 (split-K=4)
    hgemm<128, 64, 32, 32, 0><<<dim3(64, 1, ZSPLIT), 256, SMEM_G2>>>(
        (const __nv_bfloat16*)pA2, K2P,
        (const __nv_bfloat16*)pW2TS, K2P,
        (float*)pPart, K2P / ZSPLIT, nullptr);
    epi2<<<(NN * CC + 255) / 256, 256>>>(b2, out);
}